// round 13
// baseline (speedup 1.0000x reference)
#include <cuda_runtime.h>
#include <math.h>

#define BB 256
#define HW 196
#define TSi (1.0f/0.03f)
#define INV_TC (1.0f/0.07f)

// ---------------- scratch (device globals; no allocations allowed) ----------
__device__ float g_wt1[3456*512];      // conv1 weights [tap][c][n], tf32-rounded
__device__ float g_wt2[4608*512];      // conv2 weights [tap][c][n], tf32-rounded
__device__ float g_wfc1t[2048*512];    // fc1 weights transposed  [K][N]
__device__ float g_wfc2t[512*512];     // fc2 weights transposed  [K][N]
__device__ float g_evt[BB*384*HW];     // ev pre-rounded to tf32
__device__ float g_hfc[BB*512];        // relu(fc1)
__device__ float g_fa[BB*512];         // audio proj
__device__ float g_faT[512*BB];        // audio proj transposed [c][j]
__device__ float g_act1[BB*512*HW];    // relu(conv1), tf32-rounded  (b,c,p)
__device__ float g_fv[BB*512*HW];      // conv2 out    (b,c,p)
__device__ float g_ind[BB*512];        // ind_vec
__device__ float g_ivn[BB*512];        // ind_vec_norm
__device__ float g_ivnT[512*BB];       // ind_vec_norm transposed [c][j]
__device__ float g_ivnt[BB*512];       // ind_vec_norm tf32-rounded
__device__ float g_rn[BB*HW];          // 1/max(||fv[b,:,p]||, eps)
__device__ float g_Sij[BB*BB*HW];      // (i,j,p)
__device__ float g_SP[BB*BB];
__device__ float g_SN[BB*BB];
__device__ float g_l1p[BB];
__device__ float g_l2p[BB];
__device__ float g_Dm[BB*BB];          // dist*w*mask

// ---------------- helpers ---------------------------------------------------
__device__ __forceinline__ unsigned f2tf32(float x) {
    unsigned r;
    asm("cvt.rna.tf32.f32 %0, %1;" : "=r"(r) : "f"(x));
    return r;
}

__device__ __forceinline__ void mma_tf32(float* d, const unsigned* a, const unsigned* b) {
    asm volatile(
        "mma.sync.aligned.m16n8k8.row.col.f32.tf32.tf32.f32 "
        "{%0,%1,%2,%3}, {%4,%5,%6,%7}, {%8,%9}, {%0,%1,%2,%3};"
        : "+f"(d[0]), "+f"(d[1]), "+f"(d[2]), "+f"(d[3])
        : "r"(a[0]), "r"(a[1]), "r"(a[2]), "r"(a[3]), "r"(b[0]), "r"(b[1]));
}

// ---------------- weight prep: 32x32 smem tile transpose --------------------
#define T1 (108*16)
#define T2 (144*16)
#define T3 (64*16)
#define T4 (16*16)
__global__ __launch_bounds__(256) void prep_w(const float* Wc1, const float* Wc2,
                                              const float* Wf1, const float* Wf2) {
    __shared__ float s[32][33];
    int t = blockIdx.x;
    int seg, base;
    if (t < T1)                { seg = 0; base = t; }
    else if (t < T1 + T2)      { seg = 1; base = t - T1; }
    else if (t < T1 + T2 + T3) { seg = 2; base = t - T1 - T2; }
    else                       { seg = 3; base = t - T1 - T2 - T3; }

    int C  = (seg == 0) ? 384 : 512;
    int K  = (seg == 0) ? 3456 : (seg == 1) ? 4608 : (seg == 2) ? 2048 : 512;
    const float* src = (seg == 0) ? Wc1 : (seg == 1) ? Wc2 : (seg == 2) ? Wf1 : Wf2;
    float* dst = (seg == 0) ? g_wt1 : (seg == 1) ? g_wt2 : (seg == 2) ? g_wfc1t : g_wfc2t;

    int kn0 = (base >> 4) * 32;
    int o0  = (base & 15) * 32;
    int tx = threadIdx.x & 31, ty8 = threadIdx.x >> 5;

#pragma unroll
    for (int it = 0; it < 4; it++) {
        int ol = ty8 + 8 * it;
        int o = o0 + ol;
        int kn = kn0 + tx;
        int key;
        if (seg <= 1) {
            int tap = kn / C, c = kn - tap * C;
            key = c * 9 + tap;
        } else {
            key = kn;
        }
        s[tx][ol] = src[(size_t)o * K + key];
    }
    __syncthreads();
#pragma unroll
    for (int it = 0; it < 4; it++) {
        int kl = ty8 + 8 * it;
        float v = s[kl][tx];
        if (seg <= 1) v = __uint_as_float(f2tf32(v));
        dst[(size_t)(kn0 + kl) * 512 + o0 + tx] = v;
    }
}

// ---------------- pre-round ev to tf32 --------------------------------------
__global__ void round_ev(const float* ev) {
    int total = BB * 384 * HW;
    for (int i = blockIdx.x * blockDim.x + threadIdx.x; i < total;
         i += gridDim.x * blockDim.x)
        g_evt[i] = __uint_as_float(f2tf32(ev[i]));
}

// ---------------- dense GEMM (fc path): M=256, N=512, 32x64 tiles -----------
__global__ __launch_bounds__(256) void gemm_fc(const float* eaA, int mode) {
    const float* A  = (mode == 0) ? eaA : g_hfc;
    const float* Bt = (mode == 0) ? g_wfc1t : g_wfc2t;
    float* Co       = (mode == 0) ? g_hfc : g_fa;
    const int K     = (mode == 0) ? 2048 : 512;

    __shared__ float As[16][32];
    __shared__ float Bs[16][64];
    int tid = threadIdx.x;
    int m0 = blockIdx.x * 32, n0 = blockIdx.y * 64;
    int arow = tid >> 3, acol = (tid & 7) * 2;
    int brow = tid >> 4, bcol = (tid & 15) * 4;
    int tm = tid >> 4, tn = tid & 15;
    float acc[2][4] = {};

    for (int k0 = 0; k0 < K; k0 += 16) {
        float2 av = *(const float2*)(A + (m0 + arow) * K + k0 + acol);
        float4 bv = *(const float4*)(Bt + (size_t)(k0 + brow) * 512 + n0 + bcol);
        __syncthreads();
        As[acol][arow] = av.x;
        As[acol + 1][arow] = av.y;
        *(float4*)(&Bs[brow][bcol]) = bv;
        __syncthreads();
#pragma unroll
        for (int kk = 0; kk < 16; kk++) {
            float a0 = As[kk][tm], a1 = As[kk][tm + 16];
            float b0 = Bs[kk][tn], b1 = Bs[kk][tn + 16],
                  b2 = Bs[kk][tn + 32], b3 = Bs[kk][tn + 48];
            acc[0][0] += a0 * b0; acc[0][1] += a0 * b1; acc[0][2] += a0 * b2; acc[0][3] += a0 * b3;
            acc[1][0] += a1 * b0; acc[1][1] += a1 * b1; acc[1][2] += a1 * b2; acc[1][3] += a1 * b3;
        }
    }
#pragma unroll
    for (int i = 0; i < 2; i++)
#pragma unroll
        for (int j = 0; j < 4; j++) {
            float v = acc[i][j];
            int m = m0 + tm + 16 * i, n = n0 + tn + 16 * j;
            if (mode == 0) {
                Co[m * 512 + n] = fmaxf(v, 0.f);
            } else {
                Co[m * 512 + n] = v;
                g_faT[n * BB + m] = v;
            }
        }
}

// ---------------- implicit-GEMM 3x3 SAME conv via tf32 tensor cores ---------
// R9 mainloop (measured optimum) + SMEM-staged coalesced epilogue.
__global__ __launch_bounds__(256) void conv_gemm(int mode) {
    const float* in  = (mode == 0) ? g_evt : g_act1;
    const float* wt  = (mode == 0) ? g_wt1 : g_wt2;
    float* outp      = (mode == 0) ? g_act1 : g_fv;
    const int C      = (mode == 0) ? 384 : 512;
    const int relu   = (mode == 0);

    __shared__ unsigned As[2][16][136];   // [buf][k][j(m)] paired layout
    __shared__ unsigned Bs[2][16][136];   // [buf][k][n]

    int tid = threadIdx.x;
    int lane = tid & 31;
    int warp = tid >> 5;
    int warp_m = (warp & 1) * 64;
    int warp_n = (warp >> 1) * 32;

    int m0 = blockIdx.x * 128, n0 = blockIdx.y * 128;

    int ml = tid & 127, half = tid >> 7;
    int mg = m0 + ml;
    int b = mg / 196;
    int p = mg - b * 196;
    int y = p / 14;
    int x = p - y * 14;
    const float* inb = in + (size_t)b * C * 196 + half * 8 * 196;

    int mj = ((ml >> 4) << 4) + ((ml & 7) << 1) + ((ml >> 3) & 1);
    int brow = tid >> 4, bcol = (tid & 15) * 8;
    int r = lane >> 2, cq = lane & 3;
    int pbase = warp_m + r * 2;

    float acc[4][4][4] = {};

    int iy = y - 1, ix = x - 1;
    bool valid = ((unsigned)iy < 14u) && ((unsigned)ix < 14u);
    int poff = iy * 14 + ix;

    // ---- prefetch chunk 0 ----
    unsigned va[8];
    float4 bv0, bv1;
    {
        const float* src = inb + poff;
#pragma unroll
        for (int j = 0; j < 8; j++)
            va[j] = valid ? __float_as_uint(src[j * 196]) : 0u;
        const float* wrow = wt + (size_t)brow * 512 + n0 + bcol;
        bv0 = *(const float4*)(wrow);
        bv1 = *(const float4*)(wrow + 4);
    }

    int tap = 0, c0 = 0;
    const int nchunks = 9 * (C >> 4);
    for (int ci = 0; ci < nchunks; ci++) {
        int buf = ci & 1;
#pragma unroll
        for (int j = 0; j < 8; j++) As[buf][half * 8 + j][mj] = va[j];
        {
            uint4 u0 = make_uint4(__float_as_uint(bv0.x), __float_as_uint(bv0.y),
                                  __float_as_uint(bv0.z), __float_as_uint(bv0.w));
            uint4 u1 = make_uint4(__float_as_uint(bv1.x), __float_as_uint(bv1.y),
                                  __float_as_uint(bv1.z), __float_as_uint(bv1.w));
            *(uint4*)(&Bs[buf][brow][bcol])     = u0;
            *(uint4*)(&Bs[buf][brow][bcol + 4]) = u1;
        }
        __syncthreads();

        // ---- advance + prefetch next chunk ----
        int ntap = tap, nc0 = c0 + 16;
        if (nc0 == C) {
            nc0 = 0;
            ntap++;
            if (ntap < 9) {
                int dy = ntap / 3, dx = ntap - 3 * dy;
                iy = y + dy - 1; ix = x + dx - 1;
                valid = ((unsigned)iy < 14u) && ((unsigned)ix < 14u);
                poff = iy * 14 + ix;
            }
        }
        if (ci + 1 < nchunks) {
            const float* src = inb + nc0 * 196 + poff;
#pragma unroll
            for (int j = 0; j < 8; j++)
                va[j] = valid ? __float_as_uint(src[j * 196]) : 0u;
            const float* wrow = wt + ((size_t)ntap * C + nc0 + brow) * 512 + n0 + bcol;
            bv0 = *(const float4*)(wrow);
            bv1 = *(const float4*)(wrow + 4);
        }
        tap = ntap; c0 = nc0;

        // ---- MMAs on current buffer (A frags via LDS.64 pairs) ----
#pragma unroll
        for (int kk = 0; kk < 16; kk += 8) {
            unsigned afr[4][4];
#pragma unroll
            for (int mf = 0; mf < 4; mf++) {
                int cc = kk + cq;
                uint2 v01 = *(const uint2*)(&As[buf][cc][pbase + mf * 16]);
                uint2 v23 = *(const uint2*)(&As[buf][cc + 4][pbase + mf * 16]);
                afr[mf][0] = v01.x;
                afr[mf][1] = v01.y;
                afr[mf][2] = v23.x;
                afr[mf][3] = v23.y;
            }
            unsigned bfr[4][2];
#pragma unroll
            for (int nf = 0; nf < 4; nf++) {
                int bn = warp_n + nf * 8 + r;
                bfr[nf][0] = Bs[buf][kk + cq][bn];
                bfr[nf][1] = Bs[buf][kk + cq + 4][bn];
            }
#pragma unroll
            for (int mf = 0; mf < 4; mf++)
#pragma unroll
                for (int nf = 0; nf < 4; nf++)
                    mma_tf32(acc[mf][nf], afr[mf], bfr[nf]);
        }
    }

    // ---- epilogue: SMEM-staged coalesced stores, 4 passes of 32 channels ---
    float (*stage)[132] = (float(*)[132])As;   // 32*132 = 4224 <= 4352 words
    int gidx = warp * 4 + (lane >> 3);         // ch_local 0..31
    int pl = lane & 7;
#pragma unroll
    for (int pass = 0; pass < 4; pass++) {
        __syncthreads();
        if ((warp >> 1) == pass) {
#pragma unroll
            for (int mf = 0; mf < 4; mf++)
#pragma unroll
                for (int rr = 0; rr < 2; rr++) {
                    int px = warp_m + mf * 16 + r + rr * 8;
#pragma unroll
                    for (int nf = 0; nf < 4; nf++) {
                        stage[nf * 8 + 2 * cq][px]     = acc[mf][nf][rr * 2 + 0];
                        stage[nf * 8 + 2 * cq + 1][px] = acc[mf][nf][rr * 2 + 1];
                    }
                }
        }
        __syncthreads();
        int c = n0 + pass * 32 + gidx;
#pragma unroll
        for (int pb = 0; pb < 16; pb++) {
            int px = pb * 8 + pl;
            float v = stage[gidx][px];
            int mg2 = m0 + px;
            int bb = mg2 / 196, pp = mg2 - bb * 196;
            if (relu) v = __uint_as_float(f2tf32(fmaxf(v, 0.f)));
            outp[((size_t)bb * 512 + c) * 196 + pp] = v;
        }
    }
}

// ---------------- fused masked mean pooling + per-pixel norm + ivn ----------
__global__ void indrn_k(const int* masks) {
    int b = blockIdx.x;
    int tid = threadIdx.x, lane = tid & 31, warp = tid >> 5;
    __shared__ float mf[224];
    __shared__ float part[8][200];
    __shared__ float sind[512];
    __shared__ float red[256];
    __shared__ float inva_s;
    if (tid < 224) mf[tid] = (tid < 196) ? (float)masks[b * 196 + tid] : 0.f;
    __syncthreads();
    if (tid == 0) {
        float a = 0.f;
        for (int q = 0; q < 196; q++) a += mf[q];
        inva_s = 1.f / a;
    }
    float sq[7] = {};
    __syncthreads();
    float inva = inva_s;
    for (int c = warp; c < 512; c += 8) {
        const float* f = g_fv + ((size_t)b * 512 + c) * 196;
        float s = 0.f;
#pragma unroll
        for (int j = 0; j < 7; j++) {
            int q = lane + 32 * j;
            if (q < 196) {
                float v = f[q];
                s += v * mf[q];
                sq[j] += v * v;
            }
        }
#pragma unroll
        for (int o = 16; o; o >>= 1) s += __shfl_xor_sync(0xffffffffu, s, o);
        if (lane == 0) {
            float iv = s * inva;
            g_ind[b * 512 + c] = iv;
            sind[c] = iv;
        }
    }
#pragma unroll
    for (int j = 0; j < 7; j++) {
        int q = lane + 32 * j;
        if (q < 196) part[warp][q] = sq[j];
    }
    __syncthreads();
    if (tid < 196) {
        float s = 0.f;
#pragma unroll
        for (int w = 0; w < 8; w++) s += part[w][tid];
        g_rn[b * 196 + tid] = 1.f / fmaxf(sqrtf(s), 1e-12f);
    }
    // ---- fused ind_vec normalization ----
    float v0 = sind[tid], v1 = sind[tid + 256];
    red[tid] = v0 * v0 + v1 * v1;
    __syncthreads();
    for (int off = 128; off > 0; off >>= 1) {
        if (tid < off) red[tid] += red[tid + off];
        __syncthreads();
    }
    float rcp = 1.f / fmaxf(sqrtf(red[0]), 1e-12f);
    float n0 = v0 * rcp, n1 = v1 * rcp;
    g_ivn[b * 512 + tid] = n0;
    g_ivn[b * 512 + tid + 256] = n1;
    g_ivnT[tid * BB + b] = n0;
    g_ivnT[(tid + 256) * BB + b] = n1;
    g_ivnt[b * 512 + tid] = __uint_as_float(f2tf32(n0));
    g_ivnt[b * 512 + tid + 256] = __uint_as_float(f2tf32(n1));
}

// ---------------- Sij batched GEMM via tf32 MMA (paired-A LDS.64) -----------
__global__ __launch_bounds__(256) void sij_k() {
    int i = blockIdx.z;
    int n0 = blockIdx.x * 64;    // p tile
    int m0 = blockIdx.y * 128;   // j tile
    int tid = threadIdx.x;
    __shared__ unsigned As[16][136];
    __shared__ unsigned Bs[16][72];
    __shared__ float rns[64];
    int lane = tid & 31, warp = tid >> 5;
    int warp_m = (warp & 3) * 32, warp_n = (warp >> 2) * 32;
    int ml = tid & 127, half = tid >> 7;
    int brow = tid >> 4, bcol = (tid & 15) * 4;
    int r = lane >> 2, cq = lane & 3;
    int mj = ((ml >> 4) << 4) + ((ml & 7) << 1) + ((ml >> 3) & 1);
    int pbase = warp_m + r * 2;

    if (tid < 64) {
        int n = n0 + tid;
        rns[tid] = (n < 196) ? g_rn[i * 196 + n] : 0.f;
    }
    __syncthreads();

    float acc[2][4][4] = {};
    const float* fvb = g_fv + (size_t)i * 512 * 196;
    const float* arow = g_ivnt + (size_t)(m0 + ml) * 512 + half * 8;

    for (int k0 = 0; k0 < 512; k0 += 16) {
        float4 a0 = *(const float4*)(arow + k0);
        float4 a1 = *(const float4*)(arow + k0 + 4);
        float bvv[4];
#pragma unroll
        for (int q = 0; q < 4; q++) {
            int n = n0 + bcol + q;
            bvv[q] = (n < 196) ? fvb[(size_t)(k0 + brow) * 196 + n] * rns[bcol + q] : 0.f;
        }
        __syncthreads();
        int kb = half * 8;
        As[kb + 0][mj] = __float_as_uint(a0.x);
        As[kb + 1][mj] = __float_as_uint(a0.y);
        As[kb + 2][mj] = __float_as_uint(a0.z);
        As[kb + 3][mj] = __float_as_uint(a0.w);
        As[kb + 4][mj] = __float_as_uint(a1.x);
        As[kb + 5][mj] = __float_as_uint(a1.y);
        As[kb + 6][mj] = __float_as_uint(a1.z);
        As[kb + 7][mj] = __float_as_uint(a1.w);
#pragma unroll
        for (int q = 0; q < 4; q++) Bs[brow][bcol + q] = __float_as_uint(bvv[q]);
        __syncthreads();

#pragma unroll
        for (int kk = 0; kk < 16; kk += 8) {
            unsigned afr[2][4];
#pragma unroll
            for (int mf = 0; mf < 2; mf++) {
                int cc = kk + cq;
                uint2 v01 = *(const uint2*)(&As[cc][pbase + mf * 16]);
                uint2 v23 = *(const uint2*)(&As[cc + 4][pbase + mf * 16]);
                afr[mf][0] = v01.x;
                afr[mf][1] = v01.y;
                afr[mf][2] = v23.x;
                afr[mf][3] = v23.y;
            }
            unsigned bfr[4][2];
#pragma unroll
            for (int nf = 0; nf < 4; nf++) {
                int bn = warp_n + nf * 8 + r;
                bfr[nf][0] = Bs[kk + cq][bn];
                bfr[nf][1] = Bs[kk + cq + 4][bn];
            }
#pragma unroll
            for (int mf = 0; mf < 2; mf++)
#pragma unroll
                for (int nf = 0; nf < 4; nf++)
                    mma_tf32(acc[mf][nf], afr[mf], bfr[nf]);
        }
    }

#pragma unroll
    for (int mf = 0; mf < 2; mf++)
#pragma unroll
        for (int rr = 0; rr < 2; rr++) {
            int gm = m0 + warp_m + mf * 16 + r + rr * 8;
            size_t base = (size_t)i * 50176 + (size_t)gm * 196;
#pragma unroll
            for (int nf = 0; nf < 4; nf++) {
                int n = n0 + warp_n + nf * 8 + 2 * cq;
                if (n < 196)     g_Sij[base + n] = acc[mf][nf][rr * 2 + 0];
                if (n + 1 < 196) g_Sij[base + n + 1] = acc[mf][nf][rr * 2 + 1];
            }
        }
}

// ---------------- per-(i,j) thresholds via warp radix-select + SP/SN --------
__global__ __launch_bounds__(256) void topk_k() {
    int warp = threadIdx.x >> 5, lane = threadIdx.x & 31;
    int row = blockIdx.x * 8 + warp;
    const float* src = g_Sij + (size_t)row * 196;
    float v[7];
    unsigned uv[7];
#pragma unroll
    for (int j = 0; j < 7; j++) {
        int idx = lane + 32 * j;
        float f = (idx < 196) ? src[idx] : 0.f;
        v[j] = f;
        unsigned bits = __float_as_uint(f);
        unsigned u = (bits & 0x80000000u) ? ~bits : (bits | 0x80000000u);
        uv[j] = (idx < 196) ? u : 0u;
    }
    unsigned rp = 0, rq = 0;
#pragma unroll
    for (int bit = 31; bit >= 0; bit--) {
        unsigned cp = rp | (1u << bit);
        unsigned cn = rq | (1u << bit);
        int lc = 0;
#pragma unroll
        for (int j = 0; j < 7; j++) {
            lc += (uv[j] >= cp) ? 1 : 0;
            lc += (uv[j] >= cn) ? 1024 : 0;
        }
        int tot = __reduce_add_sync(0xffffffffu, lc);
        if ((tot & 1023) >= 19) rp = cp;
        if ((tot >> 10) >= 99)  rq = cn;
    }
    float pos_thr = __uint_as_float((rp & 0x80000000u) ? (rp ^ 0x80000000u) : ~rp);
    float neg_thr = __uint_as_float((rq & 0x80000000u) ? (rq ^ 0x80000000u) : ~rq);
    float s1 = 0.f, s2 = 0.f, s3 = 0.f, s4 = 0.f;
#pragma unroll
    for (int j = 0; j < 7; j++) {
        int idx = lane + 32 * j;
        if (idx < 196) {
            float mp = 1.f / (1.f + __expf(-(v[j] - pos_thr) * TSi));
            float mn = 1.f - 1.f / (1.f + __expf(-(v[j] - neg_thr) * TSi));
            s1 += v[j] * mp; s2 += mp;
            s3 += v[j] * mn; s4 += mn;
        }
    }
#pragma unroll
    for (int o = 16; o; o >>= 1) {
        s1 += __shfl_xor_sync(0xffffffffu, s1, o);
        s2 += __shfl_xor_sync(0xffffffffu, s2, o);
        s3 += __shfl_xor_sync(0xffffffffu, s3, o);
        s4 += __shfl_xor_sync(0xffffffffu, s4, o);
    }
    if (lane == 0) {
        g_SP[row] = s1 / s2;
        g_SN[row] = s3 / s4;
    }
}

// ---------------- contrastive loss rows ------------------------------------
__global__ void loss12_k() {
    int i = blockIdx.x, j = threadIdx.x;
    __shared__ float red[256];
    float diag = g_SP[i * 257] * INV_TC;
    float a1 = g_SP[i * 256 + j] * INV_TC;
    float b1 = g_SN[i * 256 + j] * INV_TC;
    red[j] = fmaxf(a1, b1);
    __syncthreads();
    for (int off = 128; off > 0; off >>= 1) {
        if (j < off) red[j] = fmaxf(red[j], red[j + off]);
        __syncthreads();
    }
    float M1 = red[0];
    __syncthreads();
    red[j] = __expf(a1 - M1) + __expf(b1 - M1);
    __syncthreads();
    for (int off = 128; off > 0; off >>= 1) {
        if (j < off) red[j] += red[j + off];
        __syncthreads();
    }
    if (j == 0) g_l1p[i] = M1 + logf(red[0]) - diag;
    __syncthreads();
    float a2 = g_SP[j * 256 + i] * INV_TC;
    float b2 = g_SN[j * 256 + i] * INV_TC;
    red[j] = fmaxf(a2, b2);
    __syncthreads();
    for (int off = 128; off > 0; off >>= 1) {
        if (j < off) red[j] = fmaxf(red[j], red[j + off]);
        __syncthreads();
    }
    float M2 = red[0];
    __syncthreads();
    red[j] = __expf(a2 - M2) + __expf(b2 - M2);
    __syncthreads();
    for (int off = 128; off > 0; off >>= 1) {
        if (j < off) red[j] += red[j + off];
        __syncthreads();
    }
    if (j == 0) g_l2p[i] = M2 + logf(red[0]) - diag;
}

// ---------------- pairwise dist * weights (coalesced via transposes) --------
__global__ void dist_k() {
    int i = blockIdx.x, j = threadIdx.x;
    __shared__ float indi[512], ivni[512];
    indi[j] = g_ind[i * 512 + j];
    indi[j + 256] = g_ind[i * 512 + j + 256];
    ivni[j] = g_ivn[i * 512 + j];
    ivni[j + 256] = g_ivn[i * 512 + j + 256];
    __syncthreads();
    float d = 0.f, vv = 0.f;
    for (int c = 0; c < 512; c++) {
        float df = indi[c] - g_faT[c * BB + j] + 1e-6f;
        d += df * df;
        vv += ivni[c] * g_ivnT[c * BB + j];
    }
    float w = (i == j) ? 1.f : -vv;
    float mm = (i == j) ? 1.f : (-1.f / 255.f);
    g_Dm[i * 256 + j] = d * w * mm;
}

// ---------------- final reduction ------------------------------------------
__global__ void finalize_k(float* out) {
    int t = threadIdx.x;
    __shared__ float s[256];
    float l1 = g_l1p[t], l2 = g_l2p[t];
    float rs = 0.f, cs = 0.f;
    for (int j = 0; j < 256; j++) {
        rs += g_Dm[t * 256 + j];
        cs += g_Dm[j * 256 + t];
    }
    float r3 = fmaxf(rs + 0.6f, 0.f);
    float r4 = fmaxf(cs + 0.6f, 0.f);
    float L1, L2, L3, L4;
#define RED_SUM(val, outv)                                       \
    __syncthreads(); s[t] = (val); __syncthreads();              \
    for (int off = 128; off > 0; off >>= 1) {                    \
        if (t < off) s[t] += s[t + off];                         \
        __syncthreads();                                         \
    }                                                            \
    outv = s[0];
    RED_SUM(l1, L1)
    RED_SUM(l2, L2)
    RED_SUM(r3, L3)
    RED_SUM(r4, L4)
#undef RED_SUM
    if (t == 0) {
        out[0] = 0.5f * (L1 + L2) * (1.f / 256.f);
        out[1] = 0.5f * (L3 + L4) * (1.f / 256.f);
    }
}

// ---------------- host ------------------------------------------------------
extern "C" void kernel_launch(void* const* d_in, const int* in_sizes, int n_in,
                              void* d_out, int out_size) {
    const float *ev = nullptr, *ea = nullptr, *Wfc1 = nullptr, *Wfc2 = nullptr,
                *Wc1 = nullptr, *Wc2 = nullptr;
    const int* masks = nullptr;
    for (int i = 0; i < n_in; i++) {
        switch (in_sizes[i]) {
            case 256 * 384 * 196: ev   = (const float*)d_in[i]; break;
            case 256 * 2048:      ea   = (const float*)d_in[i]; break;
            case 256 * 196:       masks = (const int*)d_in[i];  break;
            case 512 * 2048:      Wfc1 = (const float*)d_in[i]; break;
            case 512 * 512:       Wfc2 = (const float*)d_in[i]; break;
            case 512 * 384 * 9:   Wc1  = (const float*)d_in[i]; break;
            case 512 * 512 * 9:   Wc2  = (const float*)d_in[i]; break;
        }
    }

    prep_w<<<T1 + T2 + T3 + T4, 256>>>(Wc1, Wc2, Wfc1, Wfc2);
    round_ev<<<2048, 256>>>(ev);

    gemm_fc<<<dim3(8, 8), 256>>>(ea, 0);          // relu(fc1)
    gemm_fc<<<dim3(8, 8), 256>>>(nullptr, 1);     // fa = fc2 (+ faT)

    conv_gemm<<<dim3(392, 4), 256>>>(0);          // relu(conv1)  [staged epilogue]
    conv_gemm<<<dim3(392, 4), 256>>>(1);          // fv = conv2   [staged epilogue]

    indrn_k<<<256, 256>>>(masks);                 // fused ind + rn + ivn
    sij_k<<<dim3(4, 2, 256), 256>>>();            // tf32 MMA, paired A
    topk_k<<<8192, 256>>>();                      // warp radix-select
    loss12_k<<<256, 256>>>();
    dist_k<<<256, 256>>>();
    finalize_k<<<1, 256>>>((float*)d_out);
}

// round 14
// speedup vs baseline: 1.0354x; 1.0354x over previous
#include <cuda_runtime.h>
#include <math.h>

#define BB 256
#define HW 196
#define TSi (1.0f/0.03f)
#define INV_TC (1.0f/0.07f)

// ---------------- scratch (device globals; no allocations allowed) ----------
__device__ float g_wt1[3456*512];      // conv1 weights [tap][c][n], tf32-rounded
__device__ float g_wt2[4608*512];      // conv2 weights [tap][c][n], tf32-rounded
__device__ float g_wfc1t[2048*512];    // fc1 weights transposed  [K][N]
__device__ float g_wfc2t[512*512];     // fc2 weights transposed  [K][N]
__device__ float g_evt[BB*384*HW];     // ev pre-rounded to tf32
__device__ float g_hp0[BB*512];        // fc1 partial (K half 0)
__device__ float g_hp1[BB*512];        // fc1 partial (K half 1)
__device__ float g_hfc[BB*512];        // relu(fc1)
__device__ float g_fa[BB*512];         // audio proj
__device__ float g_faT[512*BB];        // audio proj transposed [c][j]
__device__ float g_act1[BB*512*HW];    // relu(conv1), tf32-rounded  (b,c,p)
__device__ float g_fv[BB*512*HW];      // conv2 out    (b,c,p)
__device__ float g_ind[BB*512];        // ind_vec
__device__ float g_ivn[BB*512];        // ind_vec_norm
__device__ float g_ivnT[512*BB];       // ind_vec_norm transposed [c][j]
__device__ float g_ivnt[BB*512];       // ind_vec_norm tf32-rounded
__device__ float g_rn[BB*HW];          // 1/max(||fv[b,:,p]||, eps)
__device__ float g_Sij[BB*BB*HW];      // (i,j,p)
__device__ float g_SP[BB*BB];
__device__ float g_SN[BB*BB];
__device__ float g_l1p[BB];
__device__ float g_l2p[BB];
__device__ float g_Dm[BB*BB];          // dist*w*mask

// ---------------- helpers ---------------------------------------------------
__device__ __forceinline__ unsigned f2tf32(float x) {
    unsigned r;
    asm("cvt.rna.tf32.f32 %0, %1;" : "=r"(r) : "f"(x));
    return r;
}

__device__ __forceinline__ void mma_tf32(float* d, const unsigned* a, const unsigned* b) {
    asm volatile(
        "mma.sync.aligned.m16n8k8.row.col.f32.tf32.tf32.f32 "
        "{%0,%1,%2,%3}, {%4,%5,%6,%7}, {%8,%9}, {%0,%1,%2,%3};"
        : "+f"(d[0]), "+f"(d[1]), "+f"(d[2]), "+f"(d[3])
        : "r"(a[0]), "r"(a[1]), "r"(a[2]), "r"(a[3]), "r"(b[0]), "r"(b[1]));
}

// ---------------- weight prep: 32x32 smem tile transpose --------------------
#define T1 (108*16)
#define T2 (144*16)
#define T3 (64*16)
#define T4 (16*16)
__global__ __launch_bounds__(256) void prep_w(const float* Wc1, const float* Wc2,
                                              const float* Wf1, const float* Wf2) {
    __shared__ float s[32][33];
    int t = blockIdx.x;
    int seg, base;
    if (t < T1)                { seg = 0; base = t; }
    else if (t < T1 + T2)      { seg = 1; base = t - T1; }
    else if (t < T1 + T2 + T3) { seg = 2; base = t - T1 - T2; }
    else                       { seg = 3; base = t - T1 - T2 - T3; }

    int C  = (seg == 0) ? 384 : 512;
    int K  = (seg == 0) ? 3456 : (seg == 1) ? 4608 : (seg == 2) ? 2048 : 512;
    const float* src = (seg == 0) ? Wc1 : (seg == 1) ? Wc2 : (seg == 2) ? Wf1 : Wf2;
    float* dst = (seg == 0) ? g_wt1 : (seg == 1) ? g_wt2 : (seg == 2) ? g_wfc1t : g_wfc2t;

    int kn0 = (base >> 4) * 32;
    int o0  = (base & 15) * 32;
    int tx = threadIdx.x & 31, ty8 = threadIdx.x >> 5;

#pragma unroll
    for (int it = 0; it < 4; it++) {
        int ol = ty8 + 8 * it;
        int o = o0 + ol;
        int kn = kn0 + tx;
        int key;
        if (seg <= 1) {
            int tap = kn / C, c = kn - tap * C;
            key = c * 9 + tap;
        } else {
            key = kn;
        }
        s[tx][ol] = src[(size_t)o * K + key];
    }
    __syncthreads();
#pragma unroll
    for (int it = 0; it < 4; it++) {
        int kl = ty8 + 8 * it;
        float v = s[kl][tx];
        if (seg <= 1) v = __uint_as_float(f2tf32(v));
        dst[(size_t)(kn0 + kl) * 512 + o0 + tx] = v;
    }
}

// ---------------- pre-round ev to tf32 --------------------------------------
__global__ void round_ev(const float* ev) {
    int total = BB * 384 * HW;
    for (int i = blockIdx.x * blockDim.x + threadIdx.x; i < total;
         i += gridDim.x * blockDim.x)
        g_evt[i] = __uint_as_float(f2tf32(ev[i]));
}

// ---------------- dense GEMM (fc path): M=256, N=512, 32x64 tiles -----------
// mode 0: fc1 split-K (blockIdx.z = K half -> partial buffers, no relu)
// mode 1: fc2 (full K=512, writes fa + faT)
__global__ __launch_bounds__(256) void gemm_fc(const float* eaA, int mode) {
    const float* A  = (mode == 0) ? eaA : g_hfc;
    const float* Bt = (mode == 0) ? g_wfc1t : g_wfc2t;
    const int AK    = (mode == 0) ? 2048 : 512;
    const int Kspan = (mode == 0) ? 1024 : 512;
    const int kbase = (mode == 0) ? (int)blockIdx.z * 1024 : 0;
    float* Co       = (mode == 0) ? (blockIdx.z ? g_hp1 : g_hp0) : g_fa;

    __shared__ float As[16][32];
    __shared__ float Bs[16][64];
    int tid = threadIdx.x;
    int m0 = blockIdx.x * 32, n0 = blockIdx.y * 64;
    int arow = tid >> 3, acol = (tid & 7) * 2;
    int brow = tid >> 4, bcol = (tid & 15) * 4;
    int tm = tid >> 4, tn = tid & 15;
    float acc[2][4] = {};

    for (int k0 = 0; k0 < Kspan; k0 += 16) {
        float2 av = *(const float2*)(A + (size_t)(m0 + arow) * AK + kbase + k0 + acol);
        float4 bv = *(const float4*)(Bt + (size_t)(kbase + k0 + brow) * 512 + n0 + bcol);
        __syncthreads();
        As[acol][arow] = av.x;
        As[acol + 1][arow] = av.y;
        *(float4*)(&Bs[brow][bcol]) = bv;
        __syncthreads();
#pragma unroll
        for (int kk = 0; kk < 16; kk++) {
            float a0 = As[kk][tm], a1 = As[kk][tm + 16];
            float b0 = Bs[kk][tn], b1 = Bs[kk][tn + 16],
                  b2 = Bs[kk][tn + 32], b3 = Bs[kk][tn + 48];
            acc[0][0] += a0 * b0; acc[0][1] += a0 * b1; acc[0][2] += a0 * b2; acc[0][3] += a0 * b3;
            acc[1][0] += a1 * b0; acc[1][1] += a1 * b1; acc[1][2] += a1 * b2; acc[1][3] += a1 * b3;
        }
    }
#pragma unroll
    for (int i = 0; i < 2; i++)
#pragma unroll
        for (int j = 0; j < 4; j++) {
            float v = acc[i][j];
            int m = m0 + tm + 16 * i, n = n0 + tn + 16 * j;
            if (mode == 0) {
                Co[m * 512 + n] = v;
            } else {
                Co[m * 512 + n] = v;
                g_faT[n * BB + m] = v;
            }
        }
}

// ---------------- fc1 partial sum + relu ------------------------------------
__global__ void relu_add_k() {
    int i = blockIdx.x * 256 + threadIdx.x;      // float4 index
    float4 a = ((const float4*)g_hp0)[i];
    float4 b = ((const float4*)g_hp1)[i];
    float4 o;
    o.x = fmaxf(a.x + b.x, 0.f);
    o.y = fmaxf(a.y + b.y, 0.f);
    o.z = fmaxf(a.z + b.z, 0.f);
    o.w = fmaxf(a.w + b.w, 0.f);
    ((float4*)g_hfc)[i] = o;
}

// ---------------- implicit-GEMM 3x3 SAME conv via tf32 tensor cores ---------
// R9/R12 configuration (measured optimum): 128x128 tile, 256 threads, K chunks
// of 16, double-buffered static smem, one barrier per chunk, reg-prefetch,
// paired-A layout -> LDS.64 fragments, direct per-thread epilogue stores.
__global__ __launch_bounds__(256) void conv_gemm(int mode) {
    const float* in  = (mode == 0) ? g_evt : g_act1;
    const float* wt  = (mode == 0) ? g_wt1 : g_wt2;
    float* outp      = (mode == 0) ? g_act1 : g_fv;
    const int C      = (mode == 0) ? 384 : 512;
    const int relu   = (mode == 0);

    __shared__ unsigned As[2][16][136];   // [buf][k][j(m)] paired layout
    __shared__ unsigned Bs[2][16][136];   // [buf][k][n]

    int tid = threadIdx.x;
    int lane = tid & 31;
    int warp = tid >> 5;
    int warp_m = (warp & 1) * 64;
    int warp_n = (warp >> 1) * 32;

    int m0 = blockIdx.x * 128, n0 = blockIdx.y * 128;

    int ml = tid & 127, half = tid >> 7;
    int mg = m0 + ml;
    int b = mg / 196;
    int p = mg - b * 196;
    int y = p / 14;
    int x = p - y * 14;
    const float* inb = in + (size_t)b * C * 196 + half * 8 * 196;

    int mj = ((ml >> 4) << 4) + ((ml & 7) << 1) + ((ml >> 3) & 1);
    int brow = tid >> 4, bcol = (tid & 15) * 8;
    int r = lane >> 2, cq = lane & 3;
    int pbase = warp_m + r * 2;

    float acc[4][4][4] = {};

    int iy = y - 1, ix = x - 1;
    bool valid = ((unsigned)iy < 14u) && ((unsigned)ix < 14u);
    int poff = iy * 14 + ix;

    // ---- prefetch chunk 0 ----
    unsigned va[8];
    float4 bv0, bv1;
    {
        const float* src = inb + poff;
#pragma unroll
        for (int j = 0; j < 8; j++)
            va[j] = valid ? __float_as_uint(src[j * 196]) : 0u;
        const float* wrow = wt + (size_t)brow * 512 + n0 + bcol;
        bv0 = *(const float4*)(wrow);
        bv1 = *(const float4*)(wrow + 4);
    }

    int tap = 0, c0 = 0;
    const int nchunks = 9 * (C >> 4);
    for (int ci = 0; ci < nchunks; ci++) {
        int buf = ci & 1;
#pragma unroll
        for (int j = 0; j < 8; j++) As[buf][half * 8 + j][mj] = va[j];
        {
            uint4 u0 = make_uint4(__float_as_uint(bv0.x), __float_as_uint(bv0.y),
                                  __float_as_uint(bv0.z), __float_as_uint(bv0.w));
            uint4 u1 = make_uint4(__float_as_uint(bv1.x), __float_as_uint(bv1.y),
                                  __float_as_uint(bv1.z), __float_as_uint(bv1.w));
            *(uint4*)(&Bs[buf][brow][bcol])     = u0;
            *(uint4*)(&Bs[buf][brow][bcol + 4]) = u1;
        }
        __syncthreads();

        // ---- advance + prefetch next chunk ----
        int ntap = tap, nc0 = c0 + 16;
        if (nc0 == C) {
            nc0 = 0;
            ntap++;
            if (ntap < 9) {
                int dy = ntap / 3, dx = ntap - 3 * dy;
                iy = y + dy - 1; ix = x + dx - 1;
                valid = ((unsigned)iy < 14u) && ((unsigned)ix < 14u);
                poff = iy * 14 + ix;
            }
        }
        if (ci + 1 < nchunks) {
            const float* src = inb + nc0 * 196 + poff;
#pragma unroll
            for (int j = 0; j < 8; j++)
                va[j] = valid ? __float_as_uint(src[j * 196]) : 0u;
            const float* wrow = wt + ((size_t)ntap * C + nc0 + brow) * 512 + n0 + bcol;
            bv0 = *(const float4*)(wrow);
            bv1 = *(const float4*)(wrow + 4);
        }
        tap = ntap; c0 = nc0;

        // ---- MMAs on current buffer (A frags via LDS.64 pairs) ----
#pragma unroll
        for (int kk = 0; kk < 16; kk += 8) {
            unsigned afr[4][4];
#pragma unroll
            for (int mf = 0; mf < 4; mf++) {
                int cc = kk + cq;
                uint2 v01 = *(const uint2*)(&As[buf][cc][pbase + mf * 16]);
                uint2 v23 = *(const uint2*)(&As[buf][cc + 4][pbase + mf * 16]);
                afr[mf][0] = v01.x;
                afr[mf][1] = v01.y;
                afr[mf][2] = v23.x;
                afr[mf][3] = v23.y;
            }
            unsigned bfr[4][2];
#pragma unroll
            for (int nf = 0; nf < 4; nf++) {
                int bn = warp_n + nf * 8 + r;
                bfr[nf][0] = Bs[buf][kk + cq][bn];
                bfr[nf][1] = Bs[buf][kk + cq + 4][bn];
            }
#pragma unroll
            for (int mf = 0; mf < 4; mf++)
#pragma unroll
                for (int nf = 0; nf < 4; nf++)
                    mma_tf32(acc[mf][nf], afr[mf], bfr[nf]);
        }
    }

    // ---- epilogue: direct stores (b, n, p); conv1 stores tf32-rounded relu -
#pragma unroll
    for (int mf = 0; mf < 4; mf++)
#pragma unroll
        for (int rr = 0; rr < 2; rr++) {
            int gm = m0 + warp_m + mf * 16 + r + rr * 8;
            int bb = gm / 196, pp = gm - bb * 196;
            size_t base = ((size_t)bb * 512 + n0 + warp_n) * 196 + pp;
#pragma unroll
            for (int nf = 0; nf < 4; nf++) {
                float v0 = acc[mf][nf][rr * 2 + 0];
                float v1 = acc[mf][nf][rr * 2 + 1];
                if (relu) {
                    v0 = __uint_as_float(f2tf32(fmaxf(v0, 0.f)));
                    v1 = __uint_as_float(f2tf32(fmaxf(v1, 0.f)));
                }
                size_t off = base + (size_t)(nf * 8 + 2 * cq) * 196;
                outp[off] = v0;
                outp[off + 196] = v1;
            }
        }
}

// ---------------- fused masked mean pooling + per-pixel norm + ivn ----------
__global__ void indrn_k(const int* masks) {
    int b = blockIdx.x;
    int tid = threadIdx.x, lane = tid & 31, warp = tid >> 5;
    __shared__ float mf[224];
    __shared__ float part[8][200];
    __shared__ float sind[512];
    __shared__ float red[256];
    __shared__ float inva_s;
    if (tid < 224) mf[tid] = (tid < 196) ? (float)masks[b * 196 + tid] : 0.f;
    __syncthreads();
    if (tid == 0) {
        float a = 0.f;
        for (int q = 0; q < 196; q++) a += mf[q];
        inva_s = 1.f / a;
    }
    float sq[7] = {};
    __syncthreads();
    float inva = inva_s;
    for (int c = warp; c < 512; c += 8) {
        const float* f = g_fv + ((size_t)b * 512 + c) * 196;
        float s = 0.f;
#pragma unroll
        for (int j = 0; j < 7; j++) {
            int q = lane + 32 * j;
            if (q < 196) {
                float v = f[q];
                s += v * mf[q];
                sq[j] += v * v;
            }
        }
#pragma unroll
        for (int o = 16; o; o >>= 1) s += __shfl_xor_sync(0xffffffffu, s, o);
        if (lane == 0) {
            float iv = s * inva;
            g_ind[b * 512 + c] = iv;
            sind[c] = iv;
        }
    }
#pragma unroll
    for (int j = 0; j < 7; j++) {
        int q = lane + 32 * j;
        if (q < 196) part[warp][q] = sq[j];
    }
    __syncthreads();
    if (tid < 196) {
        float s = 0.f;
#pragma unroll
        for (int w = 0; w < 8; w++) s += part[w][tid];
        g_rn[b * 196 + tid] = 1.f / fmaxf(sqrtf(s), 1e-12f);
    }
    // ---- fused ind_vec normalization ----
    float v0 = sind[tid], v1 = sind[tid + 256];
    red[tid] = v0 * v0 + v1 * v1;
    __syncthreads();
    for (int off = 128; off > 0; off >>= 1) {
        if (tid < off) red[tid] += red[tid + off];
        __syncthreads();
    }
    float rcp = 1.f / fmaxf(sqrtf(red[0]), 1e-12f);
    float n0 = v0 * rcp, n1 = v1 * rcp;
    g_ivn[b * 512 + tid] = n0;
    g_ivn[b * 512 + tid + 256] = n1;
    g_ivnT[tid * BB + b] = n0;
    g_ivnT[(tid + 256) * BB + b] = n1;
    g_ivnt[b * 512 + tid] = __uint_as_float(f2tf32(n0));
    g_ivnt[b * 512 + tid + 256] = __uint_as_float(f2tf32(n1));
}

// ---------------- Sij batched GEMM via tf32 MMA (paired-A LDS.64) -----------
__global__ __launch_bounds__(256) void sij_k() {
    int i = blockIdx.z;
    int n0 = blockIdx.x * 64;    // p tile
    int m0 = blockIdx.y * 128;   // j tile
    int tid = threadIdx.x;
    __shared__ unsigned As[16][136];
    __shared__ unsigned Bs[16][72];
    __shared__ float rns[64];
    int lane = tid & 31, warp = tid >> 5;
    int warp_m = (warp & 3) * 32, warp_n = (warp >> 2) * 32;
    int ml = tid & 127, half = tid >> 7;
    int brow = tid >> 4, bcol = (tid & 15) * 4;
    int r = lane >> 2, cq = lane & 3;
    int mj = ((ml >> 4) << 4) + ((ml & 7) << 1) + ((ml >> 3) & 1);
    int pbase = warp_m + r * 2;

    if (tid < 64) {
        int n = n0 + tid;
        rns[tid] = (n < 196) ? g_rn[i * 196 + n] : 0.f;
    }
    __syncthreads();

    float acc[2][4][4] = {};
    const float* fvb = g_fv + (size_t)i * 512 * 196;
    const float* arow = g_ivnt + (size_t)(m0 + ml) * 512 + half * 8;

    for (int k0 = 0; k0 < 512; k0 += 16) {
        float4 a0 = *(const float4*)(arow + k0);
        float4 a1 = *(const float4*)(arow + k0 + 4);
        float bvv[4];
#pragma unroll
        for (int q = 0; q < 4; q++) {
            int n = n0 + bcol + q;
            bvv[q] = (n < 196) ? fvb[(size_t)(k0 + brow) * 196 + n] * rns[bcol + q] : 0.f;
        }
        __syncthreads();
        int kb = half * 8;
        As[kb + 0][mj] = __float_as_uint(a0.x);
        As[kb + 1][mj] = __float_as_uint(a0.y);
        As[kb + 2][mj] = __float_as_uint(a0.z);
        As[kb + 3][mj] = __float_as_uint(a0.w);
        As[kb + 4][mj] = __float_as_uint(a1.x);
        As[kb + 5][mj] = __float_as_uint(a1.y);
        As[kb + 6][mj] = __float_as_uint(a1.z);
        As[kb + 7][mj] = __float_as_uint(a1.w);
#pragma unroll
        for (int q = 0; q < 4; q++) Bs[brow][bcol + q] = __float_as_uint(bvv[q]);
        __syncthreads();

#pragma unroll
        for (int kk = 0; kk < 16; kk += 8) {
            unsigned afr[2][4];
#pragma unroll
            for (int mf = 0; mf < 2; mf++) {
                int cc = kk + cq;
                uint2 v01 = *(const uint2*)(&As[cc][pbase + mf * 16]);
                uint2 v23 = *(const uint2*)(&As[cc + 4][pbase + mf * 16]);
                afr[mf][0] = v01.x;
                afr[mf][1] = v01.y;
                afr[mf][2] = v23.x;
                afr[mf][3] = v23.y;
            }
            unsigned bfr[4][2];
#pragma unroll
            for (int nf = 0; nf < 4; nf++) {
                int bn = warp_n + nf * 8 + r;
                bfr[nf][0] = Bs[kk + cq][bn];
                bfr[nf][1] = Bs[kk + cq + 4][bn];
            }
#pragma unroll
            for (int mf = 0; mf < 2; mf++)
#pragma unroll
                for (int nf = 0; nf < 4; nf++)
                    mma_tf32(acc[mf][nf], afr[mf], bfr[nf]);
        }
    }

#pragma unroll
    for (int mf = 0; mf < 2; mf++)
#pragma unroll
        for (int rr = 0; rr < 2; rr++) {
            int gm = m0 + warp_m + mf * 16 + r + rr * 8;
            size_t base = (size_t)i * 50176 + (size_t)gm * 196;
#pragma unroll
            for (int nf = 0; nf < 4; nf++) {
                int n = n0 + warp_n + nf * 8 + 2 * cq;
                if (n < 196)     g_Sij[base + n] = acc[mf][nf][rr * 2 + 0];
                if (n + 1 < 196) g_Sij[base + n + 1] = acc[mf][nf][rr * 2 + 1];
            }
        }
}

// ---------------- per-(i,j) thresholds via warp radix-select + SP/SN --------
__global__ __launch_bounds__(256) void topk_k() {
    int warp = threadIdx.x >> 5, lane = threadIdx.x & 31;
    int row = blockIdx.x * 8 + warp;
    const float* src = g_Sij + (size_t)row * 196;
    float v[7];
    unsigned uv[7];
#pragma unroll
    for (int j = 0; j < 7; j++) {
        int idx = lane + 32 * j;
        float f = (idx < 196) ? src[idx] : 0.f;
        v[j] = f;
        unsigned bits = __float_as_uint(f);
        unsigned u = (bits & 0x80000000u) ? ~bits : (bits | 0x80000000u);
        uv[j] = (idx < 196) ? u : 0u;
    }
    unsigned rp = 0, rq = 0;
#pragma unroll
    for (int bit = 31; bit >= 0; bit--) {
        unsigned cp = rp | (1u << bit);
        unsigned cn = rq | (1u << bit);
        int lc = 0;
#pragma unroll
        for (int j = 0; j < 7; j++) {
            lc += (uv[j] >= cp) ? 1 : 0;
            lc += (uv[j] >= cn) ? 1024 : 0;
        }
        int tot = __reduce_add_sync(0xffffffffu, lc);
        if ((tot & 1023) >= 19) rp = cp;
        if ((tot >> 10) >= 99)  rq = cn;
    }
    float pos_thr = __uint_as_float((rp & 0x80000000u) ? (rp ^ 0x80000000u) : ~rp);
    float neg_thr = __uint_as_float((rq & 0x80000000u) ? (rq ^ 0x80000000u) : ~rq);
    float s1 = 0.f, s2 = 0.f, s3 = 0.f, s4 = 0.f;
#pragma unroll
    for (int j = 0; j < 7; j++) {
        int idx = lane + 32 * j;
        if (idx < 196) {
            float mp = 1.f / (1.f + __expf(-(v[j] - pos_thr) * TSi));
            float mn = 1.f - 1.f / (1.f + __expf(-(v[j] - neg_thr) * TSi));
            s1 += v[j] * mp; s2 += mp;
            s3 += v[j] * mn; s4 += mn;
        }
    }
#pragma unroll
    for (int o = 16; o; o >>= 1) {
        s1 += __shfl_xor_sync(0xffffffffu, s1, o);
        s2 += __shfl_xor_sync(0xffffffffu, s2, o);
        s3 += __shfl_xor_sync(0xffffffffu, s3, o);
        s4 += __shfl_xor_sync(0xffffffffu, s4, o);
    }
    if (lane == 0) {
        g_SP[row] = s1 / s2;
        g_SN[row] = s3 / s4;
    }
}

// ---------------- contrastive loss rows ------------------------------------
__global__ void loss12_k() {
    int i = blockIdx.x, j = threadIdx.x;
    __shared__ float red[256];
    float diag = g_SP[i * 257] * INV_TC;
    float a1 = g_SP[i * 256 + j] * INV_TC;
    float b1 = g_SN[i * 256 + j] * INV_TC;
    red[j] = fmaxf(a1, b1);
    __syncthreads();
    for (int off = 128; off > 0; off >>= 1) {
        if (j < off) red[j] = fmaxf(red[j], red[j + off]);
        __syncthreads();
    }
    float M1 = red[0];
    __syncthreads();
    red[j] = __expf(a1 - M1) + __expf(b1 - M1);
    __syncthreads();
    for (int off = 128; off > 0; off >>= 1) {
        if (j < off) red[j] += red[j + off];
        __syncthreads();
    }
    if (j == 0) g_l1p[i] = M1 + logf(red[0]) - diag;
    __syncthreads();
    float a2 = g_SP[j * 256 + i] * INV_TC;
    float b2 = g_SN[j * 256 + i] * INV_TC;
    red[j] = fmaxf(a2, b2);
    __syncthreads();
    for (int off = 128; off > 0; off >>= 1) {
        if (j < off) red[j] = fmaxf(red[j], red[j + off]);
        __syncthreads();
    }
    float M2 = red[0];
    __syncthreads();
    red[j] = __expf(a2 - M2) + __expf(b2 - M2);
    __syncthreads();
    for (int off = 128; off > 0; off >>= 1) {
        if (j < off) red[j] += red[j + off];
        __syncthreads();
    }
    if (j == 0) g_l2p[i] = M2 + logf(red[0]) - diag;
}

// ---------------- pairwise dist * weights (coalesced via transposes) --------
__global__ void dist_k() {
    int i = blockIdx.x, j = threadIdx.x;
    __shared__ float indi[512], ivni[512];
    indi[j] = g_ind[i * 512 + j];
    indi[j + 256] = g_ind[i * 512 + j + 256];
    ivni[j] = g_ivn[i * 512 + j];
    ivni[j + 256] = g_ivn[i * 512 + j + 256];
    __syncthreads();
    float d = 0.f, vv = 0.f;
    for (int c = 0; c < 512; c++) {
        float df = indi[c] - g_faT[c * BB + j] + 1e-6f;
        d += df * df;
        vv += ivni[c] * g_ivnT[c * BB + j];
    }
    float w = (i == j) ? 1.f : -vv;
    float mm = (i == j) ? 1.f : (-1.f / 255.f);
    g_Dm[i * 256 + j] = d * w * mm;
}

// ---------------- final reduction ------------------------------------------
__global__ void finalize_k(float* out) {
    int t = threadIdx.x;
    __shared__ float s[256];
    float l1 = g_l1p[t], l2 = g_l2p[t];
    float rs = 0.f, cs = 0.f;
    for (int j = 0; j < 256; j++) {
        rs += g_Dm[t * 256 + j];
        cs += g_Dm[j * 256 + t];
    }
    float r3 = fmaxf(rs + 0.6f, 0.f);
    float r4 = fmaxf(cs + 0.6f, 0.f);
    float L1, L2, L3, L4;
#define RED_SUM(val, outv)                                       \
    __syncthreads(); s[t] = (val); __syncthreads();              \
    for (int off = 128; off > 0; off >>= 1) {                    \
        if (t < off) s[t] += s[t + off];                         \
        __syncthreads();                                         \
    }                                                            \
    outv = s[0];
    RED_SUM(l1, L1)
    RED_SUM(l2, L2)
    RED_SUM(r3, L3)
    RED_SUM(r4, L4)
#undef RED_SUM
    if (t == 0) {
        out[0] = 0.5f * (L1 + L2) * (1.f / 256.f);
        out[1] = 0.5f * (L3 + L4) * (1.f / 256.f);
    }
}

// ---------------- host ------------------------------------------------------
extern "C" void kernel_launch(void* const* d_in, const int* in_sizes, int n_in,
                              void* d_out, int out_size) {
    const float *ev = nullptr, *ea = nullptr, *Wfc1 = nullptr, *Wfc2 = nullptr,
                *Wc1 = nullptr, *Wc2 = nullptr;
    const int* masks = nullptr;
    for (int i = 0; i < n_in; i++) {
        switch (in_sizes[i]) {
            case 256 * 384 * 196: ev   = (const float*)d_in[i]; break;
            case 256 * 2048:      ea   = (const float*)d_in[i]; break;
            case 256 * 196:       masks = (const int*)d_in[i];  break;
            case 512 * 2048:      Wfc1 = (const float*)d_in[i]; break;
            case 512 * 512:       Wfc2 = (const float*)d_in[i]; break;
            case 512 * 384 * 9:   Wc1  = (const float*)d_in[i]; break;
            case 512 * 512 * 9:   Wc2  = (const float*)d_in[i]; break;
        }
    }

    prep_w<<<T1 + T2 + T3 + T4, 256>>>(Wc1, Wc2, Wfc1, Wfc2);
    round_ev<<<2048, 256>>>(ev);

    gemm_fc<<<dim3(8, 8, 2), 256>>>(ea, 0);       // fc1 split-K partials
    relu_add_k<<<128, 256>>>();                   // hfc = relu(p0 + p1)
    gemm_fc<<<dim3(8, 8, 1), 256>>>(nullptr, 1);  // fa = fc2 (+ faT)

    conv_gemm<<<dim3(392, 4), 256>>>(0);          // relu(conv1)  [R9 optimum]
    conv_gemm<<<dim3(392, 4), 256>>>(1);          // fv = conv2   [R9 optimum]

    indrn_k<<<256, 256>>>(masks);                 // fused ind + rn + ivn
    sij_k<<<dim3(4, 2, 256), 256>>>();            // tf32 MMA, paired A
    topk_k<<<8192, 256>>>();                      // warp radix-select
    loss12_k<<<256, 256>>>();
    dist_k<<<256, 256>>>();
    finalize_k<<<1, 256>>>((float*)d_out);
}

// round 15
// speedup vs baseline: 1.0687x; 1.0322x over previous
#include <cuda_runtime.h>
#include <math.h>

#define BB 256
#define HW 196
#define TSi (1.0f/0.03f)
#define INV_TC (1.0f/0.07f)

// ---------------- scratch (device globals; no allocations allowed) ----------
__device__ float g_wt1[3456*512];      // conv1 weights [tap][c][n], tf32-rounded
__device__ float g_wt2[4608*512];      // conv2 weights [tap][c][n], tf32-rounded
__device__ float g_wfc1t[2048*512];    // fc1 weights transposed  [K][N]
__device__ float g_wfc2t[512*512];     // fc2 weights transposed  [K][N]
__device__ float g_evt[BB*384*HW];     // ev pre-rounded to tf32
__device__ float g_hp0[BB*512];        // fc1 partial (K half 0)
__device__ float g_hp1[BB*512];        // fc1 partial (K half 1)
__device__ float g_hfc[BB*512];        // relu(fc1)
__device__ float g_fa[BB*512];         // audio proj
__device__ float g_faT[512*BB];        // audio proj transposed [c][j]
__device__ float g_act1[BB*512*HW];    // relu(conv1), tf32-rounded  (b,c,p)
__device__ float g_fv[BB*512*HW];      // conv2 out    (b,c,p)
__device__ float g_ind[BB*512];        // ind_vec
__device__ float g_ivn[BB*512];        // ind_vec_norm
__device__ float g_ivnT[512*BB];       // ind_vec_norm transposed [c][j]
__device__ float g_ivnt[BB*512];       // ind_vec_norm tf32-rounded
__device__ float g_rn[BB*HW];          // 1/max(||fv[b,:,p]||, eps)
__device__ float g_SP[BB*BB];
__device__ float g_SN[BB*BB];
__device__ float g_l1p[BB];
__device__ float g_l2p[BB];
__device__ float g_Dm[BB*BB];          // dist*w*mask

// ---------------- helpers ---------------------------------------------------
__device__ __forceinline__ unsigned f2tf32(float x) {
    unsigned r;
    asm("cvt.rna.tf32.f32 %0, %1;" : "=r"(r) : "f"(x));
    return r;
}

__device__ __forceinline__ void mma_tf32(float* d, const unsigned* a, const unsigned* b) {
    asm volatile(
        "mma.sync.aligned.m16n8k8.row.col.f32.tf32.tf32.f32 "
        "{%0,%1,%2,%3}, {%4,%5,%6,%7}, {%8,%9}, {%0,%1,%2,%3};"
        : "+f"(d[0]), "+f"(d[1]), "+f"(d[2]), "+f"(d[3])
        : "r"(a[0]), "r"(a[1]), "r"(a[2]), "r"(a[3]), "r"(b[0]), "r"(b[1]));
}

// ---------------- weight prep: 32x32 smem tile transpose --------------------
#define T1 (108*16)
#define T2 (144*16)
#define T3 (64*16)
#define T4 (16*16)
__global__ __launch_bounds__(256) void prep_w(const float* Wc1, const float* Wc2,
                                              const float* Wf1, const float* Wf2) {
    __shared__ float s[32][33];
    int t = blockIdx.x;
    int seg, base;
    if (t < T1)                { seg = 0; base = t; }
    else if (t < T1 + T2)      { seg = 1; base = t - T1; }
    else if (t < T1 + T2 + T3) { seg = 2; base = t - T1 - T2; }
    else                       { seg = 3; base = t - T1 - T2 - T3; }

    int C  = (seg == 0) ? 384 : 512;
    int K  = (seg == 0) ? 3456 : (seg == 1) ? 4608 : (seg == 2) ? 2048 : 512;
    const float* src = (seg == 0) ? Wc1 : (seg == 1) ? Wc2 : (seg == 2) ? Wf1 : Wf2;
    float* dst = (seg == 0) ? g_wt1 : (seg == 1) ? g_wt2 : (seg == 2) ? g_wfc1t : g_wfc2t;

    int kn0 = (base >> 4) * 32;
    int o0  = (base & 15) * 32;
    int tx = threadIdx.x & 31, ty8 = threadIdx.x >> 5;

#pragma unroll
    for (int it = 0; it < 4; it++) {
        int ol = ty8 + 8 * it;
        int o = o0 + ol;
        int kn = kn0 + tx;
        int key;
        if (seg <= 1) {
            int tap = kn / C, c = kn - tap * C;
            key = c * 9 + tap;
        } else {
            key = kn;
        }
        s[tx][ol] = src[(size_t)o * K + key];
    }
    __syncthreads();
#pragma unroll
    for (int it = 0; it < 4; it++) {
        int kl = ty8 + 8 * it;
        float v = s[kl][tx];
        if (seg <= 1) v = __uint_as_float(f2tf32(v));
        dst[(size_t)(kn0 + kl) * 512 + o0 + tx] = v;
    }
}

// ---------------- pre-round ev to tf32 --------------------------------------
__global__ void round_ev(const float* ev) {
    int total = BB * 384 * HW;
    for (int i = blockIdx.x * blockDim.x + threadIdx.x; i < total;
         i += gridDim.x * blockDim.x)
        g_evt[i] = __uint_as_float(f2tf32(ev[i]));
}

// ---------------- dense GEMM (fc path): M=256, N=512, 32x64 tiles -----------
__global__ __launch_bounds__(256) void gemm_fc(const float* eaA, int mode) {
    const float* A  = (mode == 0) ? eaA : g_hfc;
    const float* Bt = (mode == 0) ? g_wfc1t : g_wfc2t;
    const int AK    = (mode == 0) ? 2048 : 512;
    const int Kspan = (mode == 0) ? 1024 : 512;
    const int kbase = (mode == 0) ? (int)blockIdx.z * 1024 : 0;
    float* Co       = (mode == 0) ? (blockIdx.z ? g_hp1 : g_hp0) : g_fa;

    __shared__ float As[16][32];
    __shared__ float Bs[16][64];
    int tid = threadIdx.x;
    int m0 = blockIdx.x * 32, n0 = blockIdx.y * 64;
    int arow = tid >> 3, acol = (tid & 7) * 2;
    int brow = tid >> 4, bcol = (tid & 15) * 4;
    int tm = tid >> 4, tn = tid & 15;
    float acc[2][4] = {};

    for (int k0 = 0; k0 < Kspan; k0 += 16) {
        float2 av = *(const float2*)(A + (size_t)(m0 + arow) * AK + kbase + k0 + acol);
        float4 bv = *(const float4*)(Bt + (size_t)(kbase + k0 + brow) * 512 + n0 + bcol);
        __syncthreads();
        As[acol][arow] = av.x;
        As[acol + 1][arow] = av.y;
        *(float4*)(&Bs[brow][bcol]) = bv;
        __syncthreads();
#pragma unroll
        for (int kk = 0; kk < 16; kk++) {
            float a0 = As[kk][tm], a1 = As[kk][tm + 16];
            float b0 = Bs[kk][tn], b1 = Bs[kk][tn + 16],
                  b2 = Bs[kk][tn + 32], b3 = Bs[kk][tn + 48];
            acc[0][0] += a0 * b0; acc[0][1] += a0 * b1; acc[0][2] += a0 * b2; acc[0][3] += a0 * b3;
            acc[1][0] += a1 * b0; acc[1][1] += a1 * b1; acc[1][2] += a1 * b2; acc[1][3] += a1 * b3;
        }
    }
#pragma unroll
    for (int i = 0; i < 2; i++)
#pragma unroll
        for (int j = 0; j < 4; j++) {
            float v = acc[i][j];
            int m = m0 + tm + 16 * i, n = n0 + tn + 16 * j;
            if (mode == 0) {
                Co[m * 512 + n] = v;
            } else {
                Co[m * 512 + n] = v;
                g_faT[n * BB + m] = v;
            }
        }
}

// ---------------- fc1 partial sum + relu ------------------------------------
__global__ void relu_add_k() {
    int i = blockIdx.x * 256 + threadIdx.x;
    float4 a = ((const float4*)g_hp0)[i];
    float4 b = ((const float4*)g_hp1)[i];
    float4 o;
    o.x = fmaxf(a.x + b.x, 0.f);
    o.y = fmaxf(a.y + b.y, 0.f);
    o.z = fmaxf(a.z + b.z, 0.f);
    o.w = fmaxf(a.w + b.w, 0.f);
    ((float4*)g_hfc)[i] = o;
}

// ---------------- implicit-GEMM 3x3 SAME conv via tf32 tensor cores ---------
__global__ __launch_bounds__(256) void conv_gemm(int mode) {
    const float* in  = (mode == 0) ? g_evt : g_act1;
    const float* wt  = (mode == 0) ? g_wt1 : g_wt2;
    float* outp      = (mode == 0) ? g_act1 : g_fv;
    const int C      = (mode == 0) ? 384 : 512;
    const int relu   = (mode == 0);

    __shared__ unsigned As[2][16][136];
    __shared__ unsigned Bs[2][16][136];

    int tid = threadIdx.x;
    int lane = tid & 31;
    int warp = tid >> 5;
    int warp_m = (warp & 1) * 64;
    int warp_n = (warp >> 1) * 32;

    int m0 = blockIdx.x * 128, n0 = blockIdx.y * 128;

    int ml = tid & 127, half = tid >> 7;
    int mg = m0 + ml;
    int b = mg / 196;
    int p = mg - b * 196;
    int y = p / 14;
    int x = p - y * 14;
    const float* inb = in + (size_t)b * C * 196 + half * 8 * 196;

    int mj = ((ml >> 4) << 4) + ((ml & 7) << 1) + ((ml >> 3) & 1);
    int brow = tid >> 4, bcol = (tid & 15) * 8;
    int r = lane >> 2, cq = lane & 3;
    int pbase = warp_m + r * 2;

    float acc[4][4][4] = {};

    int iy = y - 1, ix = x - 1;
    bool valid = ((unsigned)iy < 14u) && ((unsigned)ix < 14u);
    int poff = iy * 14 + ix;

    unsigned va[8];
    float4 bv0, bv1;
    {
        const float* src = inb + poff;
#pragma unroll
        for (int j = 0; j < 8; j++)
            va[j] = valid ? __float_as_uint(src[j * 196]) : 0u;
        const float* wrow = wt + (size_t)brow * 512 + n0 + bcol;
        bv0 = *(const float4*)(wrow);
        bv1 = *(const float4*)(wrow + 4);
    }

    int tap = 0, c0 = 0;
    const int nchunks = 9 * (C >> 4);
    for (int ci = 0; ci < nchunks; ci++) {
        int buf = ci & 1;
#pragma unroll
        for (int j = 0; j < 8; j++) As[buf][half * 8 + j][mj] = va[j];
        {
            uint4 u0 = make_uint4(__float_as_uint(bv0.x), __float_as_uint(bv0.y),
                                  __float_as_uint(bv0.z), __float_as_uint(bv0.w));
            uint4 u1 = make_uint4(__float_as_uint(bv1.x), __float_as_uint(bv1.y),
                                  __float_as_uint(bv1.z), __float_as_uint(bv1.w));
            *(uint4*)(&Bs[buf][brow][bcol])     = u0;
            *(uint4*)(&Bs[buf][brow][bcol + 4]) = u1;
        }
        __syncthreads();

        int ntap = tap, nc0 = c0 + 16;
        if (nc0 == C) {
            nc0 = 0;
            ntap++;
            if (ntap < 9) {
                int dy = ntap / 3, dx = ntap - 3 * dy;
                iy = y + dy - 1; ix = x + dx - 1;
                valid = ((unsigned)iy < 14u) && ((unsigned)ix < 14u);
                poff = iy * 14 + ix;
            }
        }
        if (ci + 1 < nchunks) {
            const float* src = inb + nc0 * 196 + poff;
#pragma unroll
            for (int j = 0; j < 8; j++)
                va[j] = valid ? __float_as_uint(src[j * 196]) : 0u;
            const float* wrow = wt + ((size_t)ntap * C + nc0 + brow) * 512 + n0 + bcol;
            bv0 = *(const float4*)(wrow);
            bv1 = *(const float4*)(wrow + 4);
        }
        tap = ntap; c0 = nc0;

#pragma unroll
        for (int kk = 0; kk < 16; kk += 8) {
            unsigned afr[4][4];
#pragma unroll
            for (int mf = 0; mf < 4; mf++) {
                int cc = kk + cq;
                uint2 v01 = *(const uint2*)(&As[buf][cc][pbase + mf * 16]);
                uint2 v23 = *(const uint2*)(&As[buf][cc + 4][pbase + mf * 16]);
                afr[mf][0] = v01.x;
                afr[mf][1] = v01.y;
                afr[mf][2] = v23.x;
                afr[mf][3] = v23.y;
            }
            unsigned bfr[4][2];
#pragma unroll
            for (int nf = 0; nf < 4; nf++) {
                int bn = warp_n + nf * 8 + r;
                bfr[nf][0] = Bs[buf][kk + cq][bn];
                bfr[nf][1] = Bs[buf][kk + cq + 4][bn];
            }
#pragma unroll
            for (int mf = 0; mf < 4; mf++)
#pragma unroll
                for (int nf = 0; nf < 4; nf++)
                    mma_tf32(acc[mf][nf], afr[mf], bfr[nf]);
        }
    }

#pragma unroll
    for (int mf = 0; mf < 4; mf++)
#pragma unroll
        for (int rr = 0; rr < 2; rr++) {
            int gm = m0 + warp_m + mf * 16 + r + rr * 8;
            int bb = gm / 196, pp = gm - bb * 196;
            size_t base = ((size_t)bb * 512 + n0 + warp_n) * 196 + pp;
#pragma unroll
            for (int nf = 0; nf < 4; nf++) {
                float v0 = acc[mf][nf][rr * 2 + 0];
                float v1 = acc[mf][nf][rr * 2 + 1];
                if (relu) {
                    v0 = __uint_as_float(f2tf32(fmaxf(v0, 0.f)));
                    v1 = __uint_as_float(f2tf32(fmaxf(v1, 0.f)));
                }
                size_t off = base + (size_t)(nf * 8 + 2 * cq) * 196;
                outp[off] = v0;
                outp[off + 196] = v1;
            }
        }
}

// ---------------- fused masked mean pooling + per-pixel norm + ivn ----------
__global__ void indrn_k(const int* masks) {
    int b = blockIdx.x;
    int tid = threadIdx.x, lane = tid & 31, warp = tid >> 5;
    __shared__ float mf[224];
    __shared__ float part[8][200];
    __shared__ float sind[512];
    __shared__ float red[256];
    __shared__ float inva_s;
    if (tid < 224) mf[tid] = (tid < 196) ? (float)masks[b * 196 + tid] : 0.f;
    __syncthreads();
    if (tid == 0) {
        float a = 0.f;
        for (int q = 0; q < 196; q++) a += mf[q];
        inva_s = 1.f / a;
    }
    float sq[7] = {};
    __syncthreads();
    float inva = inva_s;
    for (int c = warp; c < 512; c += 8) {
        const float* f = g_fv + ((size_t)b * 512 + c) * 196;
        float s = 0.f;
#pragma unroll
        for (int j = 0; j < 7; j++) {
            int q = lane + 32 * j;
            if (q < 196) {
                float v = f[q];
                s += v * mf[q];
                sq[j] += v * v;
            }
        }
#pragma unroll
        for (int o = 16; o; o >>= 1) s += __shfl_xor_sync(0xffffffffu, s, o);
        if (lane == 0) {
            float iv = s * inva;
            g_ind[b * 512 + c] = iv;
            sind[c] = iv;
        }
    }
#pragma unroll
    for (int j = 0; j < 7; j++) {
        int q = lane + 32 * j;
        if (q < 196) part[warp][q] = sq[j];
    }
    __syncthreads();
    if (tid < 196) {
        float s = 0.f;
#pragma unroll
        for (int w = 0; w < 8; w++) s += part[w][tid];
        g_rn[b * 196 + tid] = 1.f / fmaxf(sqrtf(s), 1e-12f);
    }
    float v0 = sind[tid], v1 = sind[tid + 256];
    red[tid] = v0 * v0 + v1 * v1;
    __syncthreads();
    for (int off = 128; off > 0; off >>= 1) {
        if (tid < off) red[tid] += red[tid + off];
        __syncthreads();
    }
    float rcp = 1.f / fmaxf(sqrtf(red[0]), 1e-12f);
    float n0 = v0 * rcp, n1 = v1 * rcp;
    g_ivn[b * 512 + tid] = n0;
    g_ivn[b * 512 + tid + 256] = n1;
    g_ivnT[tid * BB + b] = n0;
    g_ivnT[(tid + 256) * BB + b] = n1;
    g_ivnt[b * 512 + tid] = __uint_as_float(f2tf32(n0));
    g_ivnt[b * 512 + tid + 256] = __uint_as_float(f2tf32(n1));
}

// ---------------- FUSED Sij GEMM + per-row topk/SP/SN -----------------------
// One block = (i, 32-row j tile) covering the FULL p range (196, padded 224).
// 8 warps as 2(m)x4(n); warp tile 16x56 (7 n-frags). After the mainloop the
// 32x196 tile is staged in smem and each warp radix-selects 4 rows in place.
// Sij never touches global memory.
__global__ __launch_bounds__(256) void sijtop_k() {
    int jt = blockIdx.x;         // 0..7
    int i  = blockIdx.y;         // 0..255
    int m0 = jt * 32;
    int tid = threadIdx.x;
    int lane = tid & 31, warp = tid >> 5;
    int r = lane >> 2, cq = lane & 3;
    int warp_m = (warp & 1) * 16;
    int warp_n = (warp >> 1) * 56;
    int pbase = warp_m + r * 2;

    __shared__ unsigned As[16][40];    // [k][j(m)] paired, 32 rows
    __shared__ float Bs[16][232];      // [k][p] padded 224 (+8)
    __shared__ float Sb[32][200];      // staged Sij tile
    __shared__ float rns[196];

    if (tid < 196) rns[tid] = g_rn[i * 196 + tid];
    __syncthreads();

    // A loader: row = tid>>3 (32 rows), acol = (tid&7)*2 (k pair)
    int arow = tid >> 3, acol = (tid & 7) * 2;
    int amj = ((arow >> 4) << 4) + ((arow & 7) << 1) + ((arow >> 3) & 1);
    const float* arp = g_ivnt + (size_t)(m0 + arow) * 512;
    // B loader: row = tid>>4 (16 k), cols (tid&15) + 16q
    int btr = tid >> 4, btc = tid & 15;
    const float* fvb = g_fv + (size_t)i * 512 * 196;

    float acc[7][4] = {};

    for (int k0 = 0; k0 < 512; k0 += 16) {
        float2 av = *(const float2*)(arp + k0 + acol);
        __syncthreads();
        As[acol][amj]     = __float_as_uint(av.x);
        As[acol + 1][amj] = __float_as_uint(av.y);
        const float* frow = fvb + (size_t)(k0 + btr) * 196;
#pragma unroll
        for (int q = 0; q < 14; q++) {
            int col = btc + 16 * q;
            float v = 0.f;
            if (col < 196) v = frow[col] * rns[col];
            Bs[btr][col] = v;
        }
        __syncthreads();

#pragma unroll
        for (int kk = 0; kk < 16; kk += 8) {
            int cc = kk + cq;
            unsigned afr[4];
            uint2 v01 = *(const uint2*)(&As[cc][pbase]);
            uint2 v23 = *(const uint2*)(&As[cc + 4][pbase]);
            afr[0] = v01.x; afr[1] = v01.y; afr[2] = v23.x; afr[3] = v23.y;
#pragma unroll
            for (int nf = 0; nf < 7; nf++) {
                int bn = warp_n + nf * 8 + r;
                unsigned bfr[2] = { __float_as_uint(Bs[cc][bn]),
                                    __float_as_uint(Bs[cc + 4][bn]) };
                mma_tf32(acc[nf], afr, bfr);
            }
        }
    }

    // ---- stage tile into smem ----
    __syncthreads();
#pragma unroll
    for (int nf = 0; nf < 7; nf++) {
        int col = warp_n + nf * 8 + 2 * cq;
#pragma unroll
        for (int rr = 0; rr < 2; rr++) {
            int rowl = warp_m + r + rr * 8;
            if (col < 196)     Sb[rowl][col]     = acc[nf][rr * 2 + 0];
            if (col + 1 < 196) Sb[rowl][col + 1] = acc[nf][rr * 2 + 1];
        }
    }
    __syncthreads();

    // ---- per-row radix-select + SP/SN (warp handles 4 rows) ----
    for (int rr4 = 0; rr4 < 4; rr4++) {
        int row = warp * 4 + rr4;
        float v[7];
        unsigned uv[7];
#pragma unroll
        for (int j = 0; j < 7; j++) {
            int idx = lane + 32 * j;
            float f = (idx < 196) ? Sb[row][idx] : 0.f;
            v[j] = f;
            unsigned bits = __float_as_uint(f);
            unsigned u = (bits & 0x80000000u) ? ~bits : (bits | 0x80000000u);
            uv[j] = (idx < 196) ? u : 0u;
        }
        unsigned rp = 0, rq = 0;
#pragma unroll
        for (int bit = 31; bit >= 0; bit--) {
            unsigned cp = rp | (1u << bit);
            unsigned cn = rq | (1u << bit);
            int lc = 0;
#pragma unroll
            for (int j = 0; j < 7; j++) {
                lc += (uv[j] >= cp) ? 1 : 0;
                lc += (uv[j] >= cn) ? 1024 : 0;
            }
            int tot = __reduce_add_sync(0xffffffffu, lc);
            if ((tot & 1023) >= 19) rp = cp;
            if ((tot >> 10) >= 99)  rq = cn;
        }
        float pos_thr = __uint_as_float((rp & 0x80000000u) ? (rp ^ 0x80000000u) : ~rp);
        float neg_thr = __uint_as_float((rq & 0x80000000u) ? (rq ^ 0x80000000u) : ~rq);
        float s1 = 0.f, s2 = 0.f, s3 = 0.f, s4 = 0.f;
#pragma unroll
        for (int j = 0; j < 7; j++) {
            int idx = lane + 32 * j;
            if (idx < 196) {
                float mp = 1.f / (1.f + __expf(-(v[j] - pos_thr) * TSi));
                float mn = 1.f - 1.f / (1.f + __expf(-(v[j] - neg_thr) * TSi));
                s1 += v[j] * mp; s2 += mp;
                s3 += v[j] * mn; s4 += mn;
            }
        }
#pragma unroll
        for (int o = 16; o; o >>= 1) {
            s1 += __shfl_xor_sync(0xffffffffu, s1, o);
            s2 += __shfl_xor_sync(0xffffffffu, s2, o);
            s3 += __shfl_xor_sync(0xffffffffu, s3, o);
            s4 += __shfl_xor_sync(0xffffffffu, s4, o);
        }
        if (lane == 0) {
            int rowg = i * 256 + m0 + row;
            g_SP[rowg] = s1 / s2;
            g_SN[rowg] = s3 / s4;
        }
    }
}

// ---------------- contrastive loss rows ------------------------------------
__global__ void loss12_k() {
    int i = blockIdx.x, j = threadIdx.x;
    __shared__ float red[256];
    float diag = g_SP[i * 257] * INV_TC;
    float a1 = g_SP[i * 256 + j] * INV_TC;
    float b1 = g_SN[i * 256 + j] * INV_TC;
    red[j] = fmaxf(a1, b1);
    __syncthreads();
    for (int off = 128; off > 0; off >>= 1) {
        if (j < off) red[j] = fmaxf(red[j], red[j + off]);
        __syncthreads();
    }
    float M1 = red[0];
    __syncthreads();
    red[j] = __expf(a1 - M1) + __expf(b1 - M1);
    __syncthreads();
    for (int off = 128; off > 0; off >>= 1) {
        if (j < off) red[j] += red[j + off];
        __syncthreads();
    }
    if (j == 0) g_l1p[i] = M1 + logf(red[0]) - diag;
    __syncthreads();
    float a2 = g_SP[j * 256 + i] * INV_TC;
    float b2 = g_SN[j * 256 + i] * INV_TC;
    red[j] = fmaxf(a2, b2);
    __syncthreads();
    for (int off = 128; off > 0; off >>= 1) {
        if (j < off) red[j] = fmaxf(red[j], red[j + off]);
        __syncthreads();
    }
    float M2 = red[0];
    __syncthreads();
    red[j] = __expf(a2 - M2) + __expf(b2 - M2);
    __syncthreads();
    for (int off = 128; off > 0; off >>= 1) {
        if (j < off) red[j] += red[j + off];
        __syncthreads();
    }
    if (j == 0) g_l2p[i] = M2 + logf(red[0]) - diag;
}

// ---------------- pairwise dist * weights (coalesced via transposes) --------
__global__ void dist_k() {
    int i = blockIdx.x, j = threadIdx.x;
    __shared__ float indi[512], ivni[512];
    indi[j] = g_ind[i * 512 + j];
    indi[j + 256] = g_ind[i * 512 + j + 256];
    ivni[j] = g_ivn[i * 512 + j];
    ivni[j + 256] = g_ivn[i * 512 + j + 256];
    __syncthreads();
    float d = 0.f, vv = 0.f;
    for (int c = 0; c < 512; c++) {
        float df = indi[c] - g_faT[c * BB + j] + 1e-6f;
        d += df * df;
        vv += ivni[c] * g_ivnT[c * BB + j];
    }
    float w = (i == j) ? 1.f : -vv;
    float mm = (i == j) ? 1.f : (-1.f / 255.f);
    g_Dm[i * 256 + j] = d * w * mm;
}

// ---------------- final reduction ------------------------------------------
__global__ void finalize_k(float* out) {
    int t = threadIdx.x;
    __shared__ float s[256];
    float l1 = g_l1p[t], l2 = g_l2p[t];
    float rs = 0.f, cs = 0.f;
    for (int j = 0; j < 256; j++) {
        rs += g_Dm[t * 256 + j];
        cs += g_Dm[j * 256 + t];
    }
    float r3 = fmaxf(rs + 0.6f, 0.f);
    float r4 = fmaxf(cs + 0.6f, 0.f);
    float L1, L2, L3, L4;
#define RED_SUM(val, outv)                                       \
    __syncthreads(); s[t] = (val); __syncthreads();              \
    for (int off = 128; off > 0; off >>= 1) {                    \
        if (t < off) s[t] += s[t + off];                         \
        __syncthreads();                                         \
    }                                                            \
    outv = s[0];
    RED_SUM(l1, L1)
    RED_SUM(l2, L2)
    RED_SUM(r3, L3)
    RED_SUM(r4, L4)
#undef RED_SUM
    if (t == 0) {
        out[0] = 0.5f * (L1 + L2) * (1.f / 256.f);
        out[1] = 0.5f * (L3 + L4) * (1.f / 256.f);
    }
}

// ---------------- host ------------------------------------------------------
extern "C" void kernel_launch(void* const* d_in, const int* in_sizes, int n_in,
                              void* d_out, int out_size) {
    const float *ev = nullptr, *ea = nullptr, *Wfc1 = nullptr, *Wfc2 = nullptr,
                *Wc1 = nullptr, *Wc2 = nullptr;
    const int* masks = nullptr;
    for (int i = 0; i < n_in; i++) {
        switch (in_sizes[i]) {
            case 256 * 384 * 196: ev   = (const float*)d_in[i]; break;
            case 256 * 2048:      ea   = (const float*)d_in[i]; break;
            case 256 * 196:       masks = (const int*)d_in[i];  break;
            case 512 * 2048:      Wfc1 = (const float*)d_in[i]; break;
            case 512 * 512:       Wfc2 = (const float*)d_in[i]; break;
            case 512 * 384 * 9:   Wc1  = (const float*)d_in[i]; break;
            case 512 * 512 * 9:   Wc2  = (const float*)d_in[i]; break;
        }
    }

    prep_w<<<T1 + T2 + T3 + T4, 256>>>(Wc1, Wc2, Wfc1, Wfc2);
    round_ev<<<2048, 256>>>(ev);

    gemm_fc<<<dim3(8, 8, 2), 256>>>(ea, 0);       // fc1 split-K partials
    relu_add_k<<<128, 256>>>();                   // hfc = relu(p0 + p1)
    gemm_fc<<<dim3(8, 8, 1), 256>>>(nullptr, 1);  // fa = fc2 (+ faT)

    conv_gemm<<<dim3(392, 4), 256>>>(0);          // relu(conv1)  [R9 optimum]
    conv_gemm<<<dim3(392, 4), 256>>>(1);          // fv = conv2   [R9 optimum]

    indrn_k<<<256, 256>>>(masks);                 // fused ind + rn + ivn
    sijtop_k<<<dim3(8, 256), 256>>>();            // FUSED Sij GEMM + topk
    loss12_k<<<256, 256>>>();
    dist_k<<<256, 256>>>();
    finalize_k<<<1, 256>>>((float*)d_out);
}